// round 15
// baseline (speedup 1.0000x reference)
#include <cuda_runtime.h>
#include <cstdint>

typedef unsigned long long ull;

#define H     51
#define TSEQ  512
#define FUT   64
#define TTOT  (TSEQ + FUT)
#define NT    256          // 8 warps = 2 groups x 4 warps
#define NBAT  1024
#define BPC   7            // batches per CTA: group A = 4, group B = 3
#define HRS   56           // h row stride (52 used)
#define INROW 516
#define WR    416          // weight kp-row: [A:52u x 4][B:52u x 4] k-parity packed
#define NC2   7            // cached quads, mv2 warps (Wih2@h1 stream)
#define NC1   5            // cached quads, mv1 warps (W1 stream)

// ---- smem layout (float offsets) ----
#define OFF_W1  0                   // 26 kp-rows (K=52)
#define SZ_W1   (26*WR)
#define OFF_W2  (OFF_W1 + SZ_W1)    // 52 kp-rows (K=104: h1 | h2)
#define SZ_W2   (52*WR)
#define OFF_WX  (OFF_W2 + SZ_W2)
#define OFF_B1  (OFF_WX + 256)
#define OFF_B2  (OFF_B1 + 256)
#define OFF_WL  (OFF_B2 + 256)      // 64 (bl stashed at +63, single writer)
#define OFF_GRP (OFF_WL + 64)
// per-group offsets (4-row layout kept for both groups)
#define GIN     0                   // 4 x 516
#define GH1     (4*INROW)
#define GH2     (GH1 + 2*4*HRS)
#define GRPSZ   (GH2 + 2*4*HRS)     // 2960
#define SMEM_FLOATS (OFF_GRP + 2*GRPSZ)
#define SMEM_BYTES  (SMEM_FLOATS * 4)

__device__ __forceinline__ ull ffma2(ull a, ull b, ull c) {
    ull d;
    asm("fma.rn.f32x2 %0, %1, %2, %3;" : "=l"(d) : "l"(a), "l"(b), "l"(c));
    return d;
}

__device__ __forceinline__ float foldadd(ull a) {
    float lo, hi;
    asm("mov.b64 {%0,%1}, %2;" : "=f"(lo), "=f"(hi) : "l"(a));
    return lo + hi;
}

__device__ __forceinline__ float fex2(float x) {
    float r; asm("ex2.approx.f32 %0, %1;" : "=f"(r) : "f"(x)); return r;
}
__device__ __forceinline__ float frcp(float x) {
    float r; asm("rcp.approx.f32 %0, %1;" : "=f"(r) : "f"(x)); return r;
}

// LSTM cell update, 5 EX2 + 2 RCP (validated rel err ~2.3e-7).
__device__ __forceinline__ float cellup(float gi, float gf, float gg, float go,
                                        float& c)
{
    const float L2E = 1.4426950408889634f;
    float ei = fex2(-L2E * gi);
    float ef = fex2(-L2E * gf);
    float eg = fex2(-2.0f * L2E * fabsf(gg));
    float pi = 1.0f + ei, pf = 1.0f + ef, pg = 1.0f + eg;
    float tg = copysignf(1.0f - eg, gg);
    float num = c * pi * pg + tg * pf;
    c = num * frcp(pf * pi * pg);
    float eo = fex2(-L2E * go);
    float ec = fex2(-2.0f * L2E * fabsf(c));
    return copysignf(1.0f - ec, c) * frcp((1.0f + eo) * (1.0f + ec));
}

// Full-K matvec slice: NQ quads, lane owns 4 cols (one unit), NB batches.
// First NC quads use register-cached weights; rest load from smem.
template<int NC, int NQ, int NB>
__device__ __forceinline__ void mv13c(const ull cw[][8],
                                      const float* __restrict__ wpl,
                                      const float* __restrict__ hb,
                                      ull acc[4][4])
{
    #pragma unroll
    for (int q = 0; q < NQ; ++q) {
        ull a0x, a0y, b0x, b0y, a1x, a1y, b1x, b1y;
        if (q < NC) {
            a0x = cw[q][0]; a0y = cw[q][1];
            b0x = cw[q][2]; b0y = cw[q][3];
            a1x = cw[q][4]; a1y = cw[q][5];
            b1x = cw[q][6]; b1y = cw[q][7];
        } else {
            const float* r0 = wpl + (2*q  )*WR;
            const float* r1 = wpl + (2*q+1)*WR;
            ulonglong2 wA0 = *reinterpret_cast<const ulonglong2*>(r0);
            ulonglong2 wB0 = *reinterpret_cast<const ulonglong2*>(r0 + 208);
            ulonglong2 wA1 = *reinterpret_cast<const ulonglong2*>(r1);
            ulonglong2 wB1 = *reinterpret_cast<const ulonglong2*>(r1 + 208);
            a0x = wA0.x; a0y = wA0.y; b0x = wB0.x; b0y = wB0.y;
            a1x = wA1.x; a1y = wA1.y; b1x = wB1.x; b1y = wB1.y;
        }
        #pragma unroll
        for (int b = 0; b < NB; ++b) {
            ulonglong2 hv = *reinterpret_cast<const ulonglong2*>(hb + b*HRS + 4*q);
            acc[b][0] = ffma2(a0x, hv.x, acc[b][0]);
            acc[b][1] = ffma2(a0y, hv.x, acc[b][1]);
            acc[b][2] = ffma2(b0x, hv.x, acc[b][2]);
            acc[b][3] = ffma2(b0y, hv.x, acc[b][3]);
            acc[b][0] = ffma2(a1x, hv.y, acc[b][0]);
            acc[b][1] = ffma2(a1y, hv.y, acc[b][1]);
            acc[b][2] = ffma2(b1x, hv.y, acc[b][2]);
            acc[b][3] = ffma2(b1y, hv.y, acc[b][3]);
        }
    }
}

__device__ __forceinline__ void zacc(ull acc[4][4]) {
    #pragma unroll
    for (int b = 0; b < 4; ++b) {
        #pragma unroll
        for (int c = 0; c < 4; ++c) acc[b][c] = 0ull;
    }
}

__device__ __forceinline__ void loadquad(ull dst[8], const float* __restrict__ wq)
{
    const float* r0 = wq;
    const float* r1 = wq + WR;
    ulonglong2 wA0 = *reinterpret_cast<const ulonglong2*>(r0);
    ulonglong2 wB0 = *reinterpret_cast<const ulonglong2*>(r0 + 208);
    ulonglong2 wA1 = *reinterpret_cast<const ulonglong2*>(r1);
    ulonglong2 wB1 = *reinterpret_cast<const ulonglong2*>(r1 + 208);
    dst[0] = wA0.x; dst[1] = wA0.y; dst[2] = wB0.x; dst[3] = wB0.y;
    dst[4] = wA1.x; dst[5] = wA1.y; dst[6] = wB1.x; dst[7] = wB1.y;
}

// fused gate tail: fold parities, bias (+x*wx), cellup, store plain h.
template<int NB>
__device__ __forceinline__ void gtail(ull acc[4][4], float cst[4],
                                      const float* __restrict__ bp,
                                      const float* __restrict__ wxp,
                                      const float* __restrict__ xv, bool withx,
                                      float* __restrict__ hdst, int uglob,
                                      bool act)
{
    if (!act) return;
    float4 bb = *reinterpret_cast<const float4*>(bp);
    float4 wx = withx ? *reinterpret_cast<const float4*>(wxp)
                      : make_float4(0.f, 0.f, 0.f, 0.f);
    #pragma unroll
    for (int b = 0; b < NB; ++b) {
        float gi = foldadd(acc[b][0]) + bb.x;
        float gf = foldadd(acc[b][1]) + bb.y;
        float gg = foldadd(acc[b][2]) + bb.z;
        float go = foldadd(acc[b][3]) + bb.w;
        if (withx) {
            gi = fmaf(xv[b], wx.x, gi);
            gf = fmaf(xv[b], wx.y, gf);
            gg = fmaf(xv[b], wx.z, gg);
            go = fmaf(xv[b], wx.w, go);
        }
        float hn = cellup(gi, gf, gg, go, cst[b]);
        hdst[b*HRS + uglob] = hn;
    }
}

// h2 . Wl reduce for one batch; result valid in ALL lanes (xor reduce).
__device__ __forceinline__ float outred(const float* __restrict__ h2row,
                                        const float* __restrict__ wl, int lane)
{
    float p = h2row[lane] * wl[lane];
    if (lane + 32 < H) p += h2row[lane + 32] * wl[lane + 32];
    #pragma unroll
    for (int o = 16; o > 0; o >>= 1)
        p += __shfl_xor_sync(0xffffffffu, p, o);
    return p;
}

#define GBARR(id) asm volatile("bar.sync %0, %1;" :: "r"(id), "r"(128) : "memory")

// One group's full time loop; NB = batches in this group (4 or 3).
template<int NB>
__device__ __forceinline__ void run_group(
    const float* __restrict__ sm, float* __restrict__ SG,
    float* __restrict__ out,
    int lane, int role, int barid, int bgl, int uglob, bool act)
{
    const bool ismv2 = (role < 2);
    float* h1b0 = SG + GH1;
    float* h1b1 = SG + GH1 + 4*HRS;
    float* h2b0 = SG + GH2;
    float* h2b1 = SG + GH2 + 4*HRS;
    float* OUTS = SG + GIN + 3*INROW + 512;   // 4 floats tucked in row-3 pad
    const float* wl = sm + OFF_WL;
    const float blv = sm[OFF_WL + 63];

    const float* w2p = sm + OFF_W2 + uglob*4;
    const float* w1p = sm + OFF_W1 + uglob*4;
    const float* b2p = sm + OFF_B2 + 4*uglob;
    const float* b1p = sm + OFF_B1 + 4*uglob;
    const float* wxp = sm + OFF_WX + 4*uglob;

    // register-cached weight quads (loaded once)
    ull cw[NC2][8];
    if (ismv2) {
        #pragma unroll
        for (int q = 0; q < NC2; ++q) loadquad(cw[q], w2p + 2*q*WR);
    } else {
        #pragma unroll
        for (int q = 0; q < NC1; ++q) loadquad(cw[q], w1p + 2*q*WR);
    }

    float cst[4] = {0.f, 0.f, 0.f, 0.f};

    // prologue: mv1(0) + g1(0)
    if (!ismv2) {
        ull acc[4][4]; zacc(acc);
        mv13c<NC1, 13, NB>(cw, w1p, h1b1, acc);   // h1(-1) = 0
        float xv[4];
        #pragma unroll
        for (int b = 0; b < NB; ++b) xv[b] = SG[GIN + b*INROW];
        gtail<NB>(acc, cst, b1p, wxp, xv, true, h1b0, uglob, act);
    }
    GBARR(barid);

    for (int t = 0; t < TTOT; ++t) {
        float* h1w = (((t + 1) & 1) ? h1b1 : h1b0);
        const float* h1r = ((t & 1) ? h1b1 : h1b0);
        float* h2w = ((t & 1) ? h2b1 : h2b0);
        const float* h2r = (((t + 1) & 1) ? h2b1 : h2b0);   // h2(t-1)

        if (t < TSEQ - 1) {
            // ===== main region: ONE fat phase =====
            if (ismv2) {
                ull acc[4][4]; zacc(acc);
                mv13c<NC2, 13, NB>(cw, w2p, h1r, acc);        // Wih2 @ h1(t)
                mv13c<0, 13, NB>(cw, w2p + 26*WR, h2r, acc);  // Whh2 @ h2(t-1)
                gtail<NB>(acc, cst, b2p, 0, 0, false, h2w, uglob, act);
            } else {
                if (t > 0) {                          // out(t-1), 2 batches/warp
                    int bb = (role - 2)*2;
                    if (bb < NB) {
                        float p0 = outred(h2r + bb*HRS, wl, lane);
                        if (lane == 0 && bgl + bb < NBAT)
                            out[(bgl + bb)*TTOT + (t - 1)] = p0 + blv;
                    }
                    if (bb + 1 < NB) {
                        float p1 = outred(h2r + (bb + 1)*HRS, wl, lane);
                        if (lane == 0 && bgl + bb + 1 < NBAT)
                            out[(bgl + bb + 1)*TTOT + (t - 1)] = p1 + blv;
                    }
                }
                ull acc[4][4]; zacc(acc);
                mv13c<NC1, 13, NB>(cw, w1p, h1r, acc);        // Whh1 @ h1(t)
                float xv[4];
                #pragma unroll
                for (int b = 0; b < NB; ++b)
                    xv[b] = SG[GIN + b*INROW + (t + 1)];
                gtail<NB>(acc, cst, b1p, wxp, xv, true, h1w, uglob, act);
            }
            GBARR(barid);
        } else {
            // ===== future-style step (out(t) feeds x(t+1)) =====
            if (ismv2) {
                ull acc[4][4]; zacc(acc);
                mv13c<NC2, 13, NB>(cw, w2p, h1r, acc);
                mv13c<0, 13, NB>(cw, w2p + 26*WR, h2r, acc);
                gtail<NB>(acc, cst, b2p, 0, 0, false, h2w, uglob, act);
            } else if (t == TSEQ - 1) {
                int bb = (role - 2)*2;
                if (bb < NB) {
                    float p0 = outred(h2r + bb*HRS, wl, lane);
                    if (lane == 0 && bgl + bb < NBAT)
                        out[(bgl + bb)*TTOT + (t - 1)] = p0 + blv;
                }
                if (bb + 1 < NB) {
                    float p1 = outred(h2r + (bb + 1)*HRS, wl, lane);
                    if (lane == 0 && bgl + bb + 1 < NBAT)
                        out[(bgl + bb + 1)*TTOT + (t - 1)] = p1 + blv;
                }
            }
            GBARR(barid);
            // sub-B: out(t) (all lanes), then mv1(t+1)+g1(t+1)
            if (!ismv2) {
                float xv[4];
                #pragma unroll
                for (int b = 0; b < NB; ++b)
                    xv[b] = outred(h2w + b*HRS, wl, lane) + blv;
                if (role == 2 && lane == 0) {
                    #pragma unroll
                    for (int b = 0; b < NB; ++b)
                        if (bgl + b < NBAT)
                            out[(bgl + b)*TTOT + t] = xv[b];
                }
                if (t + 1 < TTOT) {
                    ull acc[4][4]; zacc(acc);
                    mv13c<NC1, 13, NB>(cw, w1p, h1r, acc);
                    gtail<NB>(acc, cst, b1p, wxp, xv, true, h1w, uglob, act);
                }
            }
            GBARR(barid);
        }
    }
    (void)OUTS;
}

__global__ void __launch_bounds__(NT, 1)
lstm_seq_kernel(const float* __restrict__ input,
                const float* __restrict__ Wih1, const float* __restrict__ Whh1,
                const float* __restrict__ bih1, const float* __restrict__ bhh1,
                const float* __restrict__ Wih2, const float* __restrict__ Whh2,
                const float* __restrict__ bih2, const float* __restrict__ bhh2,
                const float* __restrict__ Wl,   const float* __restrict__ bl,
                float* __restrict__ out)
{
    extern __shared__ __align__(16) float sm[];
    const int tid = threadIdx.x;
    const int cb0 = blockIdx.x * BPC;

    // ---------- one-time prep ----------
    for (int idx = tid; idx < SZ_W1; idx += NT) {
        int kp = idx / WR, r = idx % WR;
        int part = (r >= 208) ? 1 : 0, rr = r - part*208;
        int u = rr >> 2, q = rr & 3;
        int c = part*2 + (q >> 1), par = q & 1;
        int k = 2*kp + par;
        sm[OFF_W1 + idx] = (u < H && k < H) ? Whh1[(c*H + u)*H + k] : 0.0f;
    }
    for (int idx = tid; idx < SZ_W2; idx += NT) {
        int kp = idx / WR, r = idx % WR;
        int part = (r >= 208) ? 1 : 0, rr = r - part*208;
        int u = rr >> 2, q = rr & 3;
        int c = part*2 + (q >> 1), par = q & 1;
        int k = 2*kp + par;          // 0..103: [h1 52 | h2 52]
        float v = 0.0f;
        if (u < H) {
            int row = (c*H + u)*H;
            if (k < H)                   v = Wih2[row + k];
            else if (k >= 52 && k < 103) v = Whh2[row + (k - 52)];
        }
        sm[OFF_W2 + idx] = v;
    }
    for (int j = tid; j < 256; j += NT) {
        int u = j >> 2, c = j & 3;
        float wx = 0.f, v1 = 0.f, v2 = 0.f;
        if (u < H && j < 208) {
            int row = c*H + u;
            wx = Wih1[row];
            v1 = bih1[row] + bhh1[row];
            v2 = bih2[row] + bhh2[row];
        }
        sm[OFF_WX + j] = wx;
        sm[OFF_B1 + j] = v1;
        sm[OFF_B2 + j] = v2;
    }
    // single writer per WL slot: 0..50 = Wl, 51..62 = 0, 63 = bl[0]
    if (tid < 64)
        sm[OFF_WL + tid] = (tid < H) ? Wl[tid]
                          : (tid == 63 ? bl[0] : 0.0f);
    // stage inputs: group A rows 0-3 = batches cb0..+3, group B rows 0-2 = +4..+6
    for (int idx = tid; idx < BPC*TSEQ; idx += NT) {
        int b = idx >> 9, tt = idx & 511;
        int gb = cb0 + b;
        int grp = (b >= 4);
        int bloc = grp ? (b - 4) : b;
        sm[OFF_GRP + grp*GRPSZ + GIN + bloc*INROW + tt]
            = (gb < NBAT) ? input[gb*TSEQ + tt] : 0.0f;
    }
    // zero unused input row 3 of group B (keeps x loads finite if touched)
    for (int idx = tid; idx < INROW; idx += NT)
        sm[OFF_GRP + GRPSZ + GIN + 3*INROW + idx] = 0.0f;
    for (int idx = tid; idx < 2*(GRPSZ - GH1); idx += NT) {
        int g = idx / (GRPSZ - GH1), r = idx % (GRPSZ - GH1);
        sm[OFF_GRP + g*GRPSZ + GH1 + r] = 0.0f;
    }
    __syncthreads();

    // ---------- roles ----------
    const int wid  = tid >> 5, lane = tid & 31;
    const int g    = wid >> 2;                    // group 0/1
    const int r4   = wid & 3;
    const int role = g ? (3 - r4) : r4;           // SMSP gets 1 heavy + 1 light
    const bool ismv2 = (role < 2);
    const int uh   = ismv2 ? role : (role - 2);
    const int uglob = uh*26 + lane;
    const bool act = (lane < 26);
    const int barid = 1 + g;
    const int bgl = cb0 + g*4;                    // group batch base

    float* SG = sm + OFF_GRP + g*GRPSZ;

    if (g == 0)
        run_group<4>(sm, SG, out, lane, role, barid, bgl, uglob, act);
    else
        run_group<3>(sm, SG, out, lane, role, barid, bgl, uglob, act);
}

extern "C" void kernel_launch(void* const* d_in, const int* in_sizes, int n_in,
                              void* d_out, int out_size)
{
    (void)n_in; (void)out_size;
    cudaFuncSetAttribute(lstm_seq_kernel,
                         cudaFuncAttributeMaxDynamicSharedMemorySize, SMEM_BYTES);
    int B = in_sizes[0] / TSEQ;                   // 1024
    int nblocks = (B + BPC - 1) / BPC;            // 147
    lstm_seq_kernel<<<nblocks, NT, SMEM_BYTES>>>(
        (const float*)d_in[0],  (const float*)d_in[1], (const float*)d_in[2],
        (const float*)d_in[3],  (const float*)d_in[4], (const float*)d_in[5],
        (const float*)d_in[6],  (const float*)d_in[7], (const float*)d_in[8],
        (const float*)d_in[9],  (const float*)d_in[10],
        (float*)d_out);
}

// round 16
// speedup vs baseline: 1.2854x; 1.2854x over previous
#include <cuda_runtime.h>
#include <cstdint>

typedef unsigned long long ull;

#define H     51
#define TSEQ  512
#define FUT   64
#define TTOT  (TSEQ + FUT)
#define NT    448          // 14 warps = 2 groups x 7 warps
#define NW    7            // warps per group
#define HRS   56           // h row stride
#define INROW 516
#define NC    4            // register-cached quads of the W2A stream

// weight layout: 3 streams (W2A = Wih2, W2B = Whh2, W1 = Whh1), each
// 13 quads; quad = 4 rows (kp0h0,kp0h1,kp1h0,kp1h1); row = 56 units x 4 floats
#define QROW    224        // floats per row
#define QSTRIDE 896        // floats per quad
#define WSTREAM (13*QSTRIDE)   // 11648
#define S_W2A 0
#define S_W2B WSTREAM
#define S_W1  (2*WSTREAM)
#define SZ_W  (3*WSTREAM)      // 34944

// ---- smem layout (float offsets) ----
#define OFF_W   0
#define OFF_WX  (OFF_W + SZ_W)
#define OFF_B1  (OFF_WX + 224)
#define OFF_B2  (OFF_B1 + 224)
#define OFF_WL  (OFF_B2 + 224)      // 64 (bl at +63, single writer)
#define OFF_GRP (OFF_WL + 64)
// per-group offsets
#define GIN   0                     // 4 x 516
#define GH    (4*INROW)             // 4 h buffers x (4 b x 56)
#define GOUT  (GH + 4*224)
#define GRPSZ (GOUT + 8)            // 2968
#define SMEM_FLOATS (OFF_GRP + 2*GRPSZ)   // ~41612 -> ~166.4 KB
#define SMEM_BYTES  (SMEM_FLOATS * 4)

__device__ __forceinline__ ull ffma2(ull a, ull b, ull c) {
    ull d;
    asm("fma.rn.f32x2 %0, %1, %2, %3;" : "=l"(d) : "l"(a), "l"(b), "l"(c));
    return d;
}

__device__ __forceinline__ float foldadd(ull a) {
    float lo, hi;
    asm("mov.b64 {%0,%1}, %2;" : "=f"(lo), "=f"(hi) : "l"(a));
    return lo + hi;
}

__device__ __forceinline__ float fex2(float x) {
    float r; asm("ex2.approx.f32 %0, %1;" : "=f"(r) : "f"(x)); return r;
}
__device__ __forceinline__ float frcp(float x) {
    float r; asm("rcp.approx.f32 %0, %1;" : "=f"(r) : "f"(x)); return r;
}

// LSTM cell update, 5 EX2 + 2 RCP (validated rel err ~2.3e-7).
__device__ __forceinline__ float cellup(float gi, float gf, float gg, float go,
                                        float& c)
{
    const float L2E = 1.4426950408889634f;
    float ei = fex2(-L2E * gi);
    float ef = fex2(-L2E * gf);
    float eg = fex2(-2.0f * L2E * fabsf(gg));
    float pi = 1.0f + ei, pf = 1.0f + ef, pg = 1.0f + eg;
    float tg = copysignf(1.0f - eg, gg);
    float num = c * pi * pg + tg * pf;
    c = num * frcp(pf * pi * pg);
    float eo = fex2(-L2E * go);
    float ec = fex2(-2.0f * L2E * fabsf(c));
    return copysignf(1.0f - ec, c) * frcp((1.0f + eo) * (1.0f + ec));
}

// Matvec over 13 quads for ONE (unit, batch) task; acc[c] = f32x2 (even, odd)
// partials for gate col c. First NCQ quads come from register cache.
// Per quad: 4 weight LDS.128 (128B dense warp-wide, 1 wf each) +
// 1 h LDS.128 (64B broadcast, 1 wf) + 8 FFMA2.
template<int NCQ>
__device__ __forceinline__ void mvq(const ull cw[][8],
                                    const float* __restrict__ lb,
                                    const float* __restrict__ hlane,
                                    ull acc[4])
{
    #pragma unroll
    for (int q = 0; q < 13; ++q) {
        ull w0x, w0y, w1x, w1y, w2x, w2y, w3x, w3y;
        if (q < NCQ) {
            w0x = cw[q][0]; w0y = cw[q][1]; w1x = cw[q][2]; w1y = cw[q][3];
            w2x = cw[q][4]; w2y = cw[q][5]; w3x = cw[q][6]; w3y = cw[q][7];
        } else {
            const float* p = lb + q*QSTRIDE;
            ulonglong2 l0 = *reinterpret_cast<const ulonglong2*>(p);           // kp0: c0,c1
            ulonglong2 l1 = *reinterpret_cast<const ulonglong2*>(p + QROW);    // kp0: c2,c3
            ulonglong2 l2 = *reinterpret_cast<const ulonglong2*>(p + 2*QROW);  // kp1: c0,c1
            ulonglong2 l3 = *reinterpret_cast<const ulonglong2*>(p + 3*QROW);  // kp1: c2,c3
            w0x = l0.x; w0y = l0.y; w1x = l1.x; w1y = l1.y;
            w2x = l2.x; w2y = l2.y; w3x = l3.x; w3y = l3.y;
        }
        ulonglong2 hv = *reinterpret_cast<const ulonglong2*>(hlane + 4*q);
        acc[0] = ffma2(w0x, hv.x, acc[0]);
        acc[1] = ffma2(w0y, hv.x, acc[1]);
        acc[2] = ffma2(w1x, hv.x, acc[2]);
        acc[3] = ffma2(w1y, hv.x, acc[3]);
        acc[0] = ffma2(w2x, hv.y, acc[0]);
        acc[1] = ffma2(w2y, hv.y, acc[1]);
        acc[2] = ffma2(w3x, hv.y, acc[2]);
        acc[3] = ffma2(w3y, hv.y, acc[3]);
    }
}

// gate tail for the lane's single (u,b) task.
__device__ __forceinline__ void gtail1(ull acc[4], float& c,
                                       const float* __restrict__ bp,
                                       const float* __restrict__ wxp,
                                       float x, bool withx,
                                       float* __restrict__ hdst, int slot)
{
    float4 bb = *reinterpret_cast<const float4*>(bp);
    float gi = foldadd(acc[0]) + bb.x;
    float gf = foldadd(acc[1]) + bb.y;
    float gg = foldadd(acc[2]) + bb.z;
    float go = foldadd(acc[3]) + bb.w;
    if (withx) {
        float4 wx = *reinterpret_cast<const float4*>(wxp);
        gi = fmaf(x, wx.x, gi);
        gf = fmaf(x, wx.y, gf);
        gg = fmaf(x, wx.z, gg);
        go = fmaf(x, wx.w, go);
    }
    hdst[slot] = cellup(gi, gf, gg, go, c);
}

// h2 . Wl reduce for one batch; result valid in ALL lanes.
__device__ __forceinline__ float outred(const float* __restrict__ h2row,
                                        const float* __restrict__ wl, int lane)
{
    float p = h2row[lane] * wl[lane];
    if (lane + 32 < H) p += h2row[lane + 32] * wl[lane + 32];
    #pragma unroll
    for (int o = 16; o > 0; o >>= 1)
        p += __shfl_xor_sync(0xffffffffu, p, o);
    return p;
}

#define GBARR(id) asm volatile("bar.sync %0, %1;" :: "r"(id), "r"(NW*32) : "memory")

__global__ void __launch_bounds__(NT, 1)
lstm_seq_kernel(const float* __restrict__ input,
                const float* __restrict__ Wih1, const float* __restrict__ Whh1,
                const float* __restrict__ bih1, const float* __restrict__ bhh1,
                const float* __restrict__ Wih2, const float* __restrict__ Whh2,
                const float* __restrict__ bih2, const float* __restrict__ bhh2,
                const float* __restrict__ Wl,   const float* __restrict__ bl,
                float* __restrict__ out)
{
    extern __shared__ __align__(16) float sm[];
    const int tid = threadIdx.x;
    const int cb0 = blockIdx.x * 8;

    // ---------- one-time prep: stream/quad/row weight layout ----------
    for (int idx = tid; idx < SZ_W; idx += NT) {
        int stream = idx / WSTREAM, r = idx % WSTREAM;
        int q = r / QSTRIDE, rr = r % QSTRIDE;
        int row = rr / QROW, rrr = rr % QROW;
        int kp = row >> 1, half = row & 1;
        int u = rrr >> 2, ci = rrr & 3;
        int col = half*2 + (ci >> 1), par = ci & 1;
        int k = q*4 + kp*2 + par;           // 0..51 within stream
        float v = 0.0f;
        if (u < H && k < H) {
            int wrow = (col*H + u)*H + k;
            v = (stream == 0) ? Wih2[wrow]
              : (stream == 1) ? Whh2[wrow]
                              : Whh1[wrow];
        }
        sm[OFF_W + idx] = v;
    }
    for (int j = tid; j < 224; j += NT) {
        int u = j >> 2, c = j & 3;
        float wx = 0.f, v1 = 0.f, v2 = 0.f;
        if (u < H) {
            int row = c*H + u;
            wx = Wih1[row];
            v1 = bih1[row] + bhh1[row];
            v2 = bih2[row] + bhh2[row];
        }
        sm[OFF_WX + j] = wx;
        sm[OFF_B1 + j] = v1;
        sm[OFF_B2 + j] = v2;
    }
    if (tid < 64)
        sm[OFF_WL + tid] = (tid < H) ? Wl[tid]
                          : (tid == 63 ? bl[0] : 0.0f);
    for (int idx = tid; idx < 8*TSEQ; idx += NT) {
        int b = idx >> 9, tt = idx & 511;
        sm[OFF_GRP + (b >> 2)*GRPSZ + GIN + (b & 3)*INROW + tt]
            = input[cb0*TSEQ + idx];
    }
    for (int idx = tid; idx < 2*(GRPSZ - GH); idx += NT) {
        int g = idx / (GRPSZ - GH), r = idx % (GRPSZ - GH);
        sm[OFF_GRP + g*GRPSZ + GH + r] = 0.0f;
    }
    __syncthreads();

    // ---------- roles: lane owns (unit, batch) ----------
    const int wid  = tid >> 5, lane = tid & 31;
    const int g    = wid / NW;                // group 0/1
    const int wg   = wid % NW;                // warp in group (0..6)
    const int u    = wg*8 + (lane >> 2);      // unit 0..55 (>=51 pad)
    const int b    = lane & 3;                // batch within group
    const int barid = 1 + g;
    const int bgl  = cb0 + g*4;

    float* SG = sm + OFF_GRP + g*GRPSZ;
    float* h1b0 = SG + GH;
    float* h1b1 = SG + GH + 224;
    float* h2b0 = SG + GH + 448;
    float* h2b1 = SG + GH + 672;
    float* OUTS = SG + GOUT;
    const float* wl = sm + OFF_WL;
    const float blv = sm[OFF_WL + 63];

    // lane-base weight pointers (stream + this lane's unit column)
    const int lb_off = u*4;
    const float* lbW2A = sm + OFF_W + S_W2A + lb_off;
    const float* lbW2B = sm + OFF_W + S_W2B + lb_off;
    const float* lbW1  = sm + OFF_W + S_W1  + lb_off;
    const float* b1p = sm + OFF_B1 + 4*u;
    const float* b2p = sm + OFF_B2 + 4*u;
    const float* wxp = sm + OFF_WX + 4*u;
    const float* xin = SG + GIN + b*INROW;

    // register-cached quads: first NC quads of the W2A stream
    ull cw[NC][8];
    #pragma unroll
    for (int q = 0; q < NC; ++q) {
        const float* p = lbW2A + q*QSTRIDE;
        ulonglong2 l0 = *reinterpret_cast<const ulonglong2*>(p);
        ulonglong2 l1 = *reinterpret_cast<const ulonglong2*>(p + QROW);
        ulonglong2 l2 = *reinterpret_cast<const ulonglong2*>(p + 2*QROW);
        ulonglong2 l3 = *reinterpret_cast<const ulonglong2*>(p + 3*QROW);
        cw[q][0] = l0.x; cw[q][1] = l0.y; cw[q][2] = l1.x; cw[q][3] = l1.y;
        cw[q][4] = l2.x; cw[q][5] = l2.y; cw[q][6] = l3.x; cw[q][7] = l3.y;
    }

    float c1 = 0.f, c2 = 0.f;
    const int hslot = b*HRS + u;

    // ---------- prologue: mv1(0) + g1(0) (h1(-1)=0 buffers) ----------
    {
        ull acc[4] = {0ull, 0ull, 0ull, 0ull};
        mvq<0>(cw, lbW1, h1b1 + b*HRS, acc);
        gtail1(acc, c1, b1p, wxp, xin[0], true, h1b0, hslot);
    }
    GBARR(barid);

    for (int t = 0; t < TTOT; ++t) {
        float* h1w = (((t + 1) & 1) ? h1b1 : h1b0);
        const float* h1r = ((t & 1) ? h1b1 : h1b0);
        float* h2w = ((t & 1) ? h2b1 : h2b0);
        const float* h2r = (((t + 1) & 1) ? h2b1 : h2b0);   // h2(t-1)

        if (t < TSEQ - 1) {
            // ===== main region: ONE phase, uniform warps =====
            if (wg < 4 && t > 0) {                 // out(t-1), 1 batch/warp
                float p = outred(h2r + wg*HRS, wl, lane);
                if (lane == 0)
                    out[(bgl + wg)*TTOT + (t - 1)] = p + blv;
            }
            {   // mv2(t): W2A@h1(t) + W2B@h2(t-1) -> h2(t)
                ull acc[4] = {0ull, 0ull, 0ull, 0ull};
                mvq<NC>(cw, lbW2A, h1r + b*HRS, acc);
                mvq<0>(cw, lbW2B, h2r + b*HRS, acc);
                gtail1(acc, c2, b2p, 0, 0.f, false, h2w, hslot);
            }
            {   // mv1(t+1): W1@h1(t) -> h1(t+1)
                ull acc[4] = {0ull, 0ull, 0ull, 0ull};
                mvq<0>(cw, lbW1, h1r + b*HRS, acc);
                gtail1(acc, c1, b1p, wxp, xin[t + 1], true, h1w, hslot);
            }
            GBARR(barid);
        } else {
            // ===== future-style step (out(t) feeds x(t+1)) =====
            if (wg < 4 && t == TSEQ - 1) {         // boundary out(TSEQ-2)
                float p = outred(h2r + wg*HRS, wl, lane);
                if (lane == 0)
                    out[(bgl + wg)*TTOT + (t - 1)] = p + blv;
            }
            {   // mv2(t)
                ull acc[4] = {0ull, 0ull, 0ull, 0ull};
                mvq<NC>(cw, lbW2A, h1r + b*HRS, acc);
                mvq<0>(cw, lbW2B, h2r + b*HRS, acc);
                gtail1(acc, c2, b2p, 0, 0.f, false, h2w, hslot);
            }
            GBARR(barid);
            if (wg < 4) {                          // out(t) -> OUTS + gmem
                float p = outred(h2w + wg*HRS, wl, lane) + blv;
                if (lane == 0) {
                    out[(bgl + wg)*TTOT + t] = p;
                    OUTS[wg] = p;
                }
            }
            GBARR(barid);
            if (t + 1 < TTOT) {                    // mv1(t+1) with x = out(t)
                ull acc[4] = {0ull, 0ull, 0ull, 0ull};
                mvq<0>(cw, lbW1, h1r + b*HRS, acc);
                gtail1(acc, c1, b1p, wxp, OUTS[b], true, h1w, hslot);
            }
            GBARR(barid);
        }
    }
}

extern "C" void kernel_launch(void* const* d_in, const int* in_sizes, int n_in,
                              void* d_out, int out_size)
{
    (void)n_in; (void)out_size;
    cudaFuncSetAttribute(lstm_seq_kernel,
                         cudaFuncAttributeMaxDynamicSharedMemorySize, SMEM_BYTES);
    int nblocks = in_sizes[0] / (TSEQ * 8);   // B / 8 = 128
    lstm_seq_kernel<<<nblocks, NT, SMEM_BYTES>>>(
        (const float*)d_in[0],  (const float*)d_in[1], (const float*)d_in[2],
        (const float*)d_in[3],  (const float*)d_in[4], (const float*)d_in[5],
        (const float*)d_in[6],  (const float*)d_in[7], (const float*)d_in[8],
        (const float*)d_in[9],  (const float*)d_in[10],
        (float*)d_out);
}

// round 17
// speedup vs baseline: 2.0270x; 1.5770x over previous
#include <cuda_runtime.h>
#include <cstdint>

typedef unsigned long long ull;

#define H     51
#define TSEQ  512
#define FUT   64
#define TTOT  (TSEQ + FUT)
#define NT    256          // 8 warps = 2 groups x 4 warps
#define HRS   56           // h row stride (52 used)
#define INROW 516
#define WR    416          // weight kp-row: [A:52u x 4][B:52u x 4] k-parity packed
#define NC2   8            // cached quads, mv2 warps (Wih2@h1 stream)
#define NC1   7            // cached quads, mv1 warps (W1 stream)

// ---- smem layout (float offsets) ----
#define OFF_W1  0                   // 26 kp-rows (K=52)
#define SZ_W1   (26*WR)
#define OFF_W2  (OFF_W1 + SZ_W1)    // 52 kp-rows (K=104: h1 | h2)
#define SZ_W2   (52*WR)
#define OFF_WX  (OFF_W2 + SZ_W2)
#define OFF_B1  (OFF_WX + 256)
#define OFF_B2  (OFF_B1 + 256)
#define OFF_WL  (OFF_B2 + 256)      // 64 (bl stashed at +63, single writer)
#define OFF_GRP (OFF_WL + 64)
// per-group offsets
#define GIN     0                   // 4 x 516
#define GH1     (4*INROW)
#define GH2     (GH1 + 2*4*HRS)
#define GRPSZ   (GH2 + 2*4*HRS)     // 2960
#define SMEM_FLOATS (OFF_GRP + 2*GRPSZ)
#define SMEM_BYTES  (SMEM_FLOATS * 4)

__device__ __forceinline__ ull ffma2(ull a, ull b, ull c) {
    ull d;
    asm("fma.rn.f32x2 %0, %1, %2, %3;" : "=l"(d) : "l"(a), "l"(b), "l"(c));
    return d;
}

__device__ __forceinline__ float foldadd(ull a) {
    float lo, hi;
    asm("mov.b64 {%0,%1}, %2;" : "=f"(lo), "=f"(hi) : "l"(a));
    return lo + hi;
}

__device__ __forceinline__ float fex2(float x) {
    float r; asm("ex2.approx.f32 %0, %1;" : "=f"(r) : "f"(x)); return r;
}
__device__ __forceinline__ float frcp(float x) {
    float r; asm("rcp.approx.f32 %0, %1;" : "=f"(r) : "f"(x)); return r;
}

// LSTM cell update, 5 EX2 + 2 RCP (validated rel err ~2.3e-7).
__device__ __forceinline__ float cellup(float gi, float gf, float gg, float go,
                                        float& c)
{
    const float L2E = 1.4426950408889634f;
    float ei = fex2(-L2E * gi);
    float ef = fex2(-L2E * gf);
    float eg = fex2(-2.0f * L2E * fabsf(gg));
    float pi = 1.0f + ei, pf = 1.0f + ef, pg = 1.0f + eg;
    float tg = copysignf(1.0f - eg, gg);
    float num = c * pi * pg + tg * pf;
    c = num * frcp(pf * pi * pg);
    float eo = fex2(-L2E * go);
    float ec = fex2(-2.0f * L2E * fabsf(c));
    return copysignf(1.0f - ec, c) * frcp((1.0f + eo) * (1.0f + ec));
}

// Full-K matvec slice: NQ quads, lane owns 4 cols (one unit), 4 batches.
// First NC quads use register-cached weights (no LDS); rest load from smem.
template<int NC, int NQ>
__device__ __forceinline__ void mv13c(const ull cw[][8],
                                      const float* __restrict__ wpl,
                                      const float* __restrict__ hb,
                                      ull acc[4][4])
{
    #pragma unroll
    for (int q = 0; q < NQ; ++q) {
        ull a0x, a0y, b0x, b0y, a1x, a1y, b1x, b1y;
        if (q < NC) {
            a0x = cw[q][0]; a0y = cw[q][1];
            b0x = cw[q][2]; b0y = cw[q][3];
            a1x = cw[q][4]; a1y = cw[q][5];
            b1x = cw[q][6]; b1y = cw[q][7];
        } else {
            const float* r0 = wpl + (2*q  )*WR;
            const float* r1 = wpl + (2*q+1)*WR;
            ulonglong2 wA0 = *reinterpret_cast<const ulonglong2*>(r0);
            ulonglong2 wB0 = *reinterpret_cast<const ulonglong2*>(r0 + 208);
            ulonglong2 wA1 = *reinterpret_cast<const ulonglong2*>(r1);
            ulonglong2 wB1 = *reinterpret_cast<const ulonglong2*>(r1 + 208);
            a0x = wA0.x; a0y = wA0.y; b0x = wB0.x; b0y = wB0.y;
            a1x = wA1.x; a1y = wA1.y; b1x = wB1.x; b1y = wB1.y;
        }
        #pragma unroll
        for (int b = 0; b < 4; ++b) {
            ulonglong2 hv = *reinterpret_cast<const ulonglong2*>(hb + b*HRS + 4*q);
            acc[b][0] = ffma2(a0x, hv.x, acc[b][0]);
            acc[b][1] = ffma2(a0y, hv.x, acc[b][1]);
            acc[b][2] = ffma2(b0x, hv.x, acc[b][2]);
            acc[b][3] = ffma2(b0y, hv.x, acc[b][3]);
            acc[b][0] = ffma2(a1x, hv.y, acc[b][0]);
            acc[b][1] = ffma2(a1y, hv.y, acc[b][1]);
            acc[b][2] = ffma2(b1x, hv.y, acc[b][2]);
            acc[b][3] = ffma2(b1y, hv.y, acc[b][3]);
        }
    }
}

__device__ __forceinline__ void zacc(ull acc[4][4]) {
    #pragma unroll
    for (int b = 0; b < 4; ++b) {
        #pragma unroll
        for (int c = 0; c < 4; ++c) acc[b][c] = 0ull;
    }
}

__device__ __forceinline__ void loadquad(ull dst[8], const float* __restrict__ wq)
{
    const float* r0 = wq;
    const float* r1 = wq + WR;
    ulonglong2 wA0 = *reinterpret_cast<const ulonglong2*>(r0);
    ulonglong2 wB0 = *reinterpret_cast<const ulonglong2*>(r0 + 208);
    ulonglong2 wA1 = *reinterpret_cast<const ulonglong2*>(r1);
    ulonglong2 wB1 = *reinterpret_cast<const ulonglong2*>(r1 + 208);
    dst[0] = wA0.x; dst[1] = wA0.y; dst[2] = wB0.x; dst[3] = wB0.y;
    dst[4] = wA1.x; dst[5] = wA1.y; dst[6] = wB1.x; dst[7] = wB1.y;
}

// fused gate tail: fold parities, bias (+x*wx), cellup, store plain h.
__device__ __forceinline__ void gtail(ull acc[4][4], float cst[4],
                                      const float* __restrict__ bp,
                                      const float* __restrict__ wxp,
                                      const float* __restrict__ xv, bool withx,
                                      float* __restrict__ hdst, int uglob,
                                      bool act)
{
    if (!act) return;
    float4 bb = *reinterpret_cast<const float4*>(bp);
    float4 wx = withx ? *reinterpret_cast<const float4*>(wxp)
                      : make_float4(0.f, 0.f, 0.f, 0.f);
    #pragma unroll
    for (int b = 0; b < 4; ++b) {
        float gi = foldadd(acc[b][0]) + bb.x;
        float gf = foldadd(acc[b][1]) + bb.y;
        float gg = foldadd(acc[b][2]) + bb.z;
        float go = foldadd(acc[b][3]) + bb.w;
        if (withx) {
            gi = fmaf(xv[b], wx.x, gi);
            gf = fmaf(xv[b], wx.y, gf);
            gg = fmaf(xv[b], wx.z, gg);
            go = fmaf(xv[b], wx.w, go);
        }
        float hn = cellup(gi, gf, gg, go, cst[b]);
        hdst[b*HRS + uglob] = hn;
    }
}

// h2 . Wl reduce for one batch; result valid in ALL lanes (xor reduce).
__device__ __forceinline__ float outred(const float* __restrict__ h2row,
                                        const float* __restrict__ wl, int lane)
{
    float p = h2row[lane] * wl[lane];
    if (lane + 32 < H) p += h2row[lane + 32] * wl[lane + 32];
    #pragma unroll
    for (int o = 16; o > 0; o >>= 1)
        p += __shfl_xor_sync(0xffffffffu, p, o);
    return p;
}

__global__ void __launch_bounds__(NT, 1)
lstm_seq_kernel(const float* __restrict__ input,
                const float* __restrict__ Wih1, const float* __restrict__ Whh1,
                const float* __restrict__ bih1, const float* __restrict__ bhh1,
                const float* __restrict__ Wih2, const float* __restrict__ Whh2,
                const float* __restrict__ bih2, const float* __restrict__ bhh2,
                const float* __restrict__ Wl,   const float* __restrict__ bl,
                float* __restrict__ out)
{
    extern __shared__ __align__(16) float sm[];
    const int tid = threadIdx.x;
    const int cb0 = blockIdx.x * 8;

    // ---------- one-time prep ----------
    for (int idx = tid; idx < SZ_W1; idx += NT) {
        int kp = idx / WR, r = idx % WR;
        int part = (r >= 208) ? 1 : 0, rr = r - part*208;
        int u = rr >> 2, q = rr & 3;
        int c = part*2 + (q >> 1), par = q & 1;
        int k = 2*kp + par;
        sm[OFF_W1 + idx] = (u < H && k < H) ? Whh1[(c*H + u)*H + k] : 0.0f;
    }
    for (int idx = tid; idx < SZ_W2; idx += NT) {
        int kp = idx / WR, r = idx % WR;
        int part = (r >= 208) ? 1 : 0, rr = r - part*208;
        int u = rr >> 2, q = rr & 3;
        int c = part*2 + (q >> 1), par = q & 1;
        int k = 2*kp + par;          // 0..103: [h1 52 | h2 52]
        float v = 0.0f;
        if (u < H) {
            int row = (c*H + u)*H;
            if (k < H)                   v = Wih2[row + k];
            else if (k >= 52 && k < 103) v = Whh2[row + (k - 52)];
        }
        sm[OFF_W2 + idx] = v;
    }
    for (int j = tid; j < 256; j += NT) {
        int u = j >> 2, c = j & 3;
        float wx = 0.f, v1 = 0.f, v2 = 0.f;
        if (u < H && j < 208) {
            int row = c*H + u;
            wx = Wih1[row];
            v1 = bih1[row] + bhh1[row];
            v2 = bih2[row] + bhh2[row];
        }
        sm[OFF_WX + j] = wx;
        sm[OFF_B1 + j] = v1;
        sm[OFF_B2 + j] = v2;
    }
    // single writer per WL slot: 0..50 = Wl, 51..62 = 0, 63 = bl[0]
    if (tid < 64)
        sm[OFF_WL + tid] = (tid < H) ? Wl[tid]
                          : (tid == 63 ? bl[0] : 0.0f);
    for (int idx = tid; idx < 8*TSEQ; idx += NT) {
        int b = idx >> 9, tt = idx & 511;
        sm[OFF_GRP + (b >> 2)*GRPSZ + GIN + (b & 3)*INROW + tt]
            = input[cb0*TSEQ + idx];
    }
    for (int idx = tid; idx < 2*(GRPSZ - GH1); idx += NT) {
        int g = idx / (GRPSZ - GH1), r = idx % (GRPSZ - GH1);
        sm[OFF_GRP + g*GRPSZ + GH1 + r] = 0.0f;
    }
    __syncthreads();

    // ---------- roles ----------
    const int wid  = tid >> 5, lane = tid & 31;
    const int g    = wid >> 2;                    // group 0/1
    const int r4   = wid & 3;
    const int role = g ? (3 - r4) : r4;           // SMSP gets 1 heavy + 1 light
    const bool ismv2 = (role < 2);
    const int uh   = ismv2 ? role : (role - 2);   // unit-half
    const int uglob = uh*26 + lane;               // unit (lanes >=26 inactive)
    const bool act = (lane < 26);
    const int barid = 1 + g;

    float* SG = sm + OFF_GRP + g*GRPSZ;
    float* h1b0 = SG + GH1;
    float* h1b1 = SG + GH1 + 4*HRS;
    float* h2b0 = SG + GH2;
    float* h2b1 = SG + GH2 + 4*HRS;
    const float* wl = sm + OFF_WL;
    const float blv = sm[OFF_WL + 63];

    const float* w2p = sm + OFF_W2 + uglob*4;
    const float* w1p = sm + OFF_W1 + uglob*4;
    const float* b2p = sm + OFF_B2 + 4*uglob;
    const float* b1p = sm + OFF_B1 + 4*uglob;
    const float* wxp = sm + OFF_WX + 4*uglob;
    const int bgl = cb0 + g*4;

    // ---------- register-cached weight quads (loaded once) ----------
    ull cw[NC2][8];
    if (ismv2) {
        #pragma unroll
        for (int q = 0; q < NC2; ++q) loadquad(cw[q], w2p + 2*q*WR);
    } else {
        #pragma unroll
        for (int q = 0; q < NC1; ++q) loadquad(cw[q], w1p + 2*q*WR);
    }

    float cst[4] = {0.f, 0.f, 0.f, 0.f};    // c2 (mv2 warps) / c1 (mv1 warps)

    #define GBAR() asm volatile("bar.sync %0, %1;" :: "r"(barid), "r"(128) : "memory")

    // ---------- prologue: mv1(0) + g1(0) ----------
    if (!ismv2) {
        ull acc[4][4]; zacc(acc);
        mv13c<NC1, 13>(cw, w1p, h1b1, acc);     // h1(-1) = 0
        float xv[4];
        #pragma unroll
        for (int b = 0; b < 4; ++b) xv[b] = SG[GIN + b*INROW];
        gtail(acc, cst, b1p, wxp, xv, true, h1b0, uglob, act);
    }
    GBAR();

    for (int t = 0; t < TTOT; ++t) {
        float* h1w = (((t + 1) & 1) ? h1b1 : h1b0);
        const float* h1r = ((t & 1) ? h1b1 : h1b0);
        float* h2w = ((t & 1) ? h2b1 : h2b0);
        const float* h2r = (((t + 1) & 1) ? h2b1 : h2b0);   // h2(t-1)

        if (t < TSEQ - 1) {
            // ===== main region: ONE fat phase =====
            if (ismv2) {
                ull acc[4][4]; zacc(acc);
                mv13c<NC2, 13>(cw, w2p, h1r, acc);         // Wih2 @ h1(t)
                mv13c<0, 13>(cw, w2p + 26*WR, h2r, acc);   // Whh2 @ h2(t-1)
                gtail(acc, cst, b2p, 0, 0, false, h2w, uglob, act);
            } else {
                if (t > 0) {                          // out(t-1), 2 batches/warp
                    int bb = (role - 2)*2;
                    float p0 = outred(h2r + bb*HRS, wl, lane);
                    float p1 = outred(h2r + (bb + 1)*HRS, wl, lane);
                    if (lane == 0) {
                        out[(bgl + bb    )*TTOT + (t - 1)] = p0 + blv;
                        out[(bgl + bb + 1)*TTOT + (t - 1)] = p1 + blv;
                    }
                }
                ull acc[4][4]; zacc(acc);
                mv13c<NC1, 13>(cw, w1p, h1r, acc);         // Whh1 @ h1(t)
                float xv[4];
                #pragma unroll
                for (int b = 0; b < 4; ++b)
                    xv[b] = SG[GIN + b*INROW + (t + 1)];
                gtail(acc, cst, b1p, wxp, xv, true, h1w, uglob, act);
            }
            GBAR();
        } else {
            // ===== future-style step (out(t) feeds x(t+1)) =====
            if (ismv2) {
                ull acc[4][4]; zacc(acc);
                mv13c<NC2, 13>(cw, w2p, h1r, acc);
                mv13c<0, 13>(cw, w2p + 26*WR, h2r, acc);
                gtail(acc, cst, b2p, 0, 0, false, h2w, uglob, act);
            } else if (t == TSEQ - 1) {
                int bb = (role - 2)*2;
                float p0 = outred(h2r + bb*HRS, wl, lane);
                float p1 = outred(h2r + (bb + 1)*HRS, wl, lane);
                if (lane == 0) {
                    out[(bgl + bb    )*TTOT + (t - 1)] = p0 + blv;
                    out[(bgl + bb + 1)*TTOT + (t - 1)] = p1 + blv;
                }
            }
            GBAR();
            // sub-B: out(t) (all lanes get value), then mv1(t+1)+g1(t+1)
            if (!ismv2) {
                float xv[4];
                #pragma unroll
                for (int b = 0; b < 4; ++b)
                    xv[b] = outred(h2w + b*HRS, wl, lane) + blv;
                if (role == 2 && lane == 0) {
                    #pragma unroll
                    for (int b = 0; b < 4; ++b)
                        out[(bgl + b)*TTOT + t] = xv[b];
                }
                if (t + 1 < TTOT) {
                    ull acc[4][4]; zacc(acc);
                    mv13c<NC1, 13>(cw, w1p, h1r, acc);
                    gtail(acc, cst, b1p, wxp, xv, true, h1w, uglob, act);
                }
            }
            GBAR();
        }
    }
    #undef GBAR
}

extern "C" void kernel_launch(void* const* d_in, const int* in_sizes, int n_in,
                              void* d_out, int out_size)
{
    (void)n_in; (void)out_size;
    cudaFuncSetAttribute(lstm_seq_kernel,
                         cudaFuncAttributeMaxDynamicSharedMemorySize, SMEM_BYTES);
    int nblocks = in_sizes[0] / (TSEQ * 8);   // B / 8 = 128
    lstm_seq_kernel<<<nblocks, NT, SMEM_BYTES>>>(
        (const float*)d_in[0],  (const float*)d_in[1], (const float*)d_in[2],
        (const float*)d_in[3],  (const float*)d_in[4], (const float*)d_in[5],
        (const float*)d_in[6],  (const float*)d_in[7], (const float*)d_in[8],
        (const float*)d_in[9],  (const float*)d_in[10],
        (float*)d_out);
}